// round 1
// baseline (speedup 1.0000x reference)
#include <cuda_runtime.h>
#include <stdint.h>

// keep[b][n] = 1 if node n is in the top-k of batch b. Max B=16, N=2048.
__device__ unsigned char g_keep[16 * 2048];

// ---------------------------------------------------------------------------
// Kernel 1: exact top-k selection by rank counting.
// rank(i) = #{ j : s[j] > s[i]  OR  (s[j] == s[i] AND j < i) }
// keep iff rank < k  — identical selection set to jax.lax.top_k (ties -> lower idx).
// Grid: B * (N/128) blocks, 128 threads. Scores for the batch staged in SMEM.
// ---------------------------------------------------------------------------
__global__ void topk_select_kernel(const float* __restrict__ score,
                                   int N, int k, int blocksPerBatch) {
    __shared__ float s[2048];
    int b     = blockIdx.x / blocksPerBatch;
    int chunk = blockIdx.x % blocksPerBatch;

    const float* sc = score + (size_t)b * N;
    for (int i = threadIdx.x; i < N; i += blockDim.x) s[i] = sc[i];
    __syncthreads();

    int i = chunk * blockDim.x + threadIdx.x;
    if (i < N) {
        float v = s[i];
        int cnt = 0;
#pragma unroll 8
        for (int j = 0; j < N; j++) {
            float u = s[j];
            cnt += (int)((u > v) || (u == v && j < i));
        }
        g_keep[b * N + i] = (cnt < k) ? 1u : 0u;
    }
}

// ---------------------------------------------------------------------------
// Kernel 2: out[b,i,j] = adj[b,i,j] * (keep[b,i] || keep[b,j])
// One block per (b,i) row. Row flag is block-uniform:
//   kept row    -> straight float4 copy
//   dropped row -> multiply by column keep (uchar4 from L1-resident g_keep)
// Pure streaming: ~2.1 GB total traffic, HBM-bound.
// ---------------------------------------------------------------------------
__global__ void apply_mask_kernel(const float4* __restrict__ adj,
                                  float4* __restrict__ out, int N) {
    int row = blockIdx.x;              // 0 .. B*N-1
    int b   = row / N;
    int i   = row - b * N;

    const unsigned char* kb = g_keep + b * N;
    bool row_kept = (kb[i] != 0);

    int    nvec = N >> 2;              // float4 per row
    size_t base = (size_t)row * nvec;

    if (row_kept) {
        for (int j = threadIdx.x; j < nvec; j += blockDim.x) {
            out[base + j] = adj[base + j];
        }
    } else {
        const uchar4* km = (const uchar4*)kb;
        for (int j = threadIdx.x; j < nvec; j += blockDim.x) {
            float4 v = adj[base + j];
            uchar4 m = km[j];
            v.x = m.x ? v.x : 0.0f;
            v.y = m.y ? v.y : 0.0f;
            v.z = m.z ? v.z : 0.0f;
            v.w = m.w ? v.w : 0.0f;
            out[base + j] = v;
        }
    }
}

extern "C" void kernel_launch(void* const* d_in, const int* in_sizes, int n_in,
                              void* d_out, int out_size) {
    const float* adj   = (const float*)d_in[0];   // [B, N, N] fp32
    const float* score = (const float*)d_in[1];   // [B, N, 1] fp32

    long long n_adj   = in_sizes[0];
    long long n_score = in_sizes[1];
    int N = (int)(n_adj / n_score);               // 2048
    int B = (int)(n_score / N);                   // 16
    int k = N / 2;                                // RATE = 0.5

    // 1) compute keep mask (exact top-k with lax.top_k tie-break)
    int tpb = 128;
    int blocksPerBatch = (N + tpb - 1) / tpb;
    topk_select_kernel<<<B * blocksPerBatch, tpb>>>(score, N, k, blocksPerBatch);

    // 2) stream adj -> out with row/col union mask
    apply_mask_kernel<<<B * N, 256>>>((const float4*)adj, (float4*)d_out, N);
}

// round 2
// speedup vs baseline: 1.0775x; 1.0775x over previous
#include <cuda_runtime.h>
#include <stdint.h>

// keep[b][n] = 1 if node n is in the top-k of batch b. B=16, N=2048.
__device__ unsigned char g_keep[16 * 2048];

// ---------------------------------------------------------------------------
// Kernel 1: exact top-k via bitonic sort of 64-bit composite keys.
// key = (~orderable(score) << 32) | index
//   - orderable(f): monotone float->uint map (flip sign bit, or all bits if neg)
//   - ascending sort of key == descending by value, ties -> lower index first
//   - identical selection set to jax.lax.top_k. Keys unique (index in low bits).
// One block per batch, 1024 threads, N=2048 elements in SMEM.
// 66 compare-exchange passes; ~1M total ops vs 67M for rank counting.
// ---------------------------------------------------------------------------
__global__ void topk_bitonic_kernel(const float* __restrict__ score,
                                    int N, int k) {
    __shared__ unsigned long long keys[2048];
    int b   = blockIdx.x;
    int tid = threadIdx.x;
    const float* sc = score + (size_t)b * N;

    for (int t = tid; t < N; t += blockDim.x) {
        unsigned u = __float_as_uint(sc[t]);
        u ^= (u & 0x80000000u) ? 0xFFFFFFFFu : 0x80000000u;   // order-preserving
        keys[t] = ((unsigned long long)(~u) << 32) | (unsigned)t;
    }
    __syncthreads();

    for (int k2 = 2; k2 <= N; k2 <<= 1) {
        for (int j = k2 >> 1; j > 0; j >>= 1) {
            for (int p = tid; p < (N >> 1); p += blockDim.x) {
                int a  = ((p & ~(j - 1)) << 1) | (p & (j - 1));
                int bb = a | j;
                bool asc = ((a & k2) == 0);
                unsigned long long ka = keys[a], kb = keys[bb];
                if ((ka > kb) == asc) { keys[a] = kb; keys[bb] = ka; }
            }
            __syncthreads();
        }
    }

    // sorted ascending by composite key == descending by score
    for (int p = tid; p < N; p += blockDim.x) {
        unsigned idx = (unsigned)(keys[p] & 0xFFFFFFFFu);
        g_keep[b * N + idx] = (p < k) ? 1u : 0u;
    }
}

// ---------------------------------------------------------------------------
// Kernel 2: out[b,i,j] = adj[b,i,j] * (keep[b,i] || keep[b,j])
// One block per (b,i) row; row flag is block-uniform.
// Streaming .cs hints: 268MB tensors don't fit 126MB L2, don't cache.
// ---------------------------------------------------------------------------
__global__ void apply_mask_kernel(const float4* __restrict__ adj,
                                  float4* __restrict__ out, int N) {
    int row = blockIdx.x;              // 0 .. B*N-1
    int b   = row / N;
    int i   = row - b * N;

    const unsigned char* kb = g_keep + b * N;
    bool row_kept = (kb[i] != 0);

    int    nvec = N >> 2;
    size_t base = (size_t)row * nvec;

    if (row_kept) {
        for (int j = threadIdx.x; j < nvec; j += blockDim.x) {
            float4 v = __ldcs(&adj[base + j]);
            __stcs(&out[base + j], v);
        }
    } else {
        const uchar4* km = (const uchar4*)kb;   // 2KB, L1-resident
        for (int j = threadIdx.x; j < nvec; j += blockDim.x) {
            float4 v = __ldcs(&adj[base + j]);
            uchar4 m = km[j];
            v.x = m.x ? v.x : 0.0f;
            v.y = m.y ? v.y : 0.0f;
            v.z = m.z ? v.z : 0.0f;
            v.w = m.w ? v.w : 0.0f;
            __stcs(&out[base + j], v);
        }
    }
}

extern "C" void kernel_launch(void* const* d_in, const int* in_sizes, int n_in,
                              void* d_out, int out_size) {
    const float* adj   = (const float*)d_in[0];   // [B, N, N] fp32
    const float* score = (const float*)d_in[1];   // [B, N, 1] fp32

    long long n_adj   = in_sizes[0];
    long long n_score = in_sizes[1];
    int N = (int)(n_adj / n_score);               // 2048
    int B = (int)(n_score / N);                   // 16
    int k = N / 2;                                // RATE = 0.5

    topk_bitonic_kernel<<<B, 1024>>>(score, N, k);
    apply_mask_kernel<<<B * N, 256>>>((const float4*)adj, (float4*)d_out, N);
}